// round 17
// baseline (speedup 1.0000x reference)
#include <cuda_runtime.h>
#include <cuda_fp16.h>
#include <math.h>
#include <stdint.h>

// Problem constants
constexpr int Bb = 2, Ss = 2048, Dd = 1024, Hh = 16, DH = 64;
constexpr int MM = Bb * Ss;       // 4096 rows

// ---------------- scratch (no cudaMalloc allowed) ----------------
__device__ __half g_x16[MM * Dd];
__device__ __half g_q16[MM * Dd];     // pre-scaled by SCL2 (log2-domain QK)
__device__ __half g_k16[MM * Dd];
__device__ __half g_v16[MM * Dd];
__device__ __half g_a16[MM * Dd];
__device__ __half g_wt16[4 * Dd * Dd];    // transposed weights [N,K], Wq|Wk|Wv|Wo

constexpr float SCL2 = 0.03125f * 1.4426950408889634f;   // (1/32) * log2(e)

// ================= helpers =================
__device__ __forceinline__ uint32_t smem_u32(const void* p) {
    uint32_t a;
    asm("{ .reg .u64 t; cvta.to.shared.u64 t, %1; cvt.u32.u64 %0, t; }" : "=r"(a) : "l"(p));
    return a;
}
__device__ __forceinline__ void ldsm_x4(uint32_t* r, uint32_t a) {
    asm volatile("ldmatrix.sync.aligned.m8n8.x4.shared.b16 {%0,%1,%2,%3}, [%4];"
                 : "=r"(r[0]), "=r"(r[1]), "=r"(r[2]), "=r"(r[3]) : "r"(a));
}
__device__ __forceinline__ void ldsm_x4_t(uint32_t* r, uint32_t a) {
    asm volatile("ldmatrix.sync.aligned.m8n8.x4.trans.shared.b16 {%0,%1,%2,%3}, [%4];"
                 : "=r"(r[0]), "=r"(r[1]), "=r"(r[2]), "=r"(r[3]) : "r"(a));
}
__device__ __forceinline__ void mma_f16(float* c, const uint32_t* a, const uint32_t* b) {
    asm volatile("mma.sync.aligned.m16n8k16.row.col.f32.f16.f16.f32 "
                 "{%0,%1,%2,%3}, {%4,%5,%6,%7}, {%8,%9}, {%0,%1,%2,%3};"
                 : "+f"(c[0]), "+f"(c[1]), "+f"(c[2]), "+f"(c[3])
                 : "r"(a[0]), "r"(a[1]), "r"(a[2]), "r"(a[3]), "r"(b[0]), "r"(b[1]));
}
__device__ __forceinline__ void cp16(uint32_t dst, const void* src) {
    asm volatile("cp.async.cg.shared.global [%0], [%1], 16;" :: "r"(dst), "l"(src));
}
#define CP_COMMIT() asm volatile("cp.async.commit_group;" ::: "memory")
#define CP_WAIT(n)  asm volatile("cp.async.wait_group %0;" :: "n"(n) : "memory")
#define SWZ128(off) ((off) ^ (((off) >> 3) & 0x70))

__device__ __forceinline__ uint32_t pkh2(float a, float b) {
    __half2 h = __floats2half2_rn(a, b);
    return *(uint32_t*)&h;
}
__device__ __forceinline__ uint32_t ex2_h2(uint32_t v) {
    uint32_t r;
    asm volatile("ex2.approx.f16x2 %0, %1;" : "=r"(r) : "r"(v));
    return r;
}

// ================= prep kernel (fused) =================
// z in 0..3 -> transpose W_z; z in 4..7 -> x fp32->fp16 (4 slices x 1024 CTAs)
__global__ __launch_bounds__(256) void prep_all(
    const float* __restrict__ x,
    const float* __restrict__ W0, const float* __restrict__ W1,
    const float* __restrict__ W2, const float* __restrict__ W3,
    __half* __restrict__ x16, __half* __restrict__ wt16)
{
    if (blockIdx.z >= 4) {
        int i = (((int)blockIdx.z - 4) * 1024 + (int)blockIdx.y * 32 + (int)blockIdx.x) * 256
                + (int)threadIdx.x;
        float4 v = ((const float4*)x)[i];
        uint2 p;
        p.x = pkh2(v.x, v.y);
        p.y = pkh2(v.z, v.w);
        ((uint2*)x16)[i] = p;
        return;
    }
    __shared__ float sm[32][33];
    const float* W = (blockIdx.z == 0) ? W0 : (blockIdx.z == 1) ? W1 : (blockIdx.z == 2) ? W2 : W3;
    const int tx = threadIdx.x & 31, ty = threadIdx.x >> 5;
    const int k0 = blockIdx.y * 32, n0 = blockIdx.x * 32;
#pragma unroll
    for (int i = 0; i < 4; i++)
        sm[ty + 8 * i][tx] = W[(size_t)(k0 + ty + 8 * i) * Dd + n0 + tx];
    __syncthreads();
    size_t zb = (size_t)blockIdx.z * Dd * Dd;
#pragma unroll
    for (int i = 0; i < 4; i++) {
        float v = sm[tx][ty + 8 * i];
        wt16[zb + (size_t)(n0 + ty + 8 * i) * Dd + k0 + tx] = __float2half_rn(v);
    }
}

// ================= mma.sync GEMM (fp16, 3-stage ring, 1 barrier/iter) ==========
// MODE 0: QKV (z==0 output pre-scaled by SCL2). MODE 1: O projection, fp32 out.
constexpr int BM = 128, BN = 128, BKC = 64;
constexpr int STG_BYTES = 32768;               // A 16K | B 16K
constexpr int OFF_A = 0, OFF_B = 16384;
constexpr int GEMM_SMEM = 3 * STG_BYTES + 1024;

template<int MODE>
__global__ __launch_bounds__(256, 2) void gemm_mma(
    const float* __restrict__ bias0, const float* __restrict__ bias1,
    const float* __restrict__ bias2, float* __restrict__ C)
{
    extern __shared__ char smc[];
    uint32_t sraw = smem_u32(smc);
    uint32_t sb = (sraw + 1023u) & ~1023u;

    const int tid = threadIdx.x, lid = tid & 31, wid = tid >> 5;
    const int wm = wid >> 2, wn = wid & 3;
    const int m0 = blockIdx.y * BM;
    const int z = (MODE == 0) ? (blockIdx.x >> 3) : 3;
    const int n0 = (MODE == 0) ? ((blockIdx.x & 7) * BN) : (blockIdx.x * BN);

    const __half* A = (MODE == 0) ? g_x16 : g_a16;
    const __half* B = g_wt16 + (size_t)z * Dd * Dd;
    const float* bias = (MODE == 1) ? bias0 : ((z == 0) ? bias0 : (z == 1) ? bias1 : bias2);
    __half* Cq = nullptr;
    if (MODE == 0) Cq = (z == 0) ? g_q16 : (z == 1) ? g_k16 : g_v16;
    const float oscl = (MODE == 0 && z == 0) ? SCL2 : 1.0f;

    uint32_t dsto[4];
    int rowA[4], rowB[4];
    uint32_t coff[4];
#pragma unroll
    for (int i = 0; i < 4; i++) {
        int idx = tid + i * 256;
        int r = idx >> 3;
        uint32_t off = (uint32_t)(r * 128 + (idx & 7) * 16);
        dsto[i] = SWZ128(off);
        rowA[i] = m0 + r;
        rowB[i] = n0 + r;
        coff[i] = (uint32_t)((idx & 7) * 16);
    }

    auto prefetch = [&](int chunk) {
        uint32_t st = sb + (chunk % 3) * STG_BYTES;
        size_t kb = (size_t)chunk * BKC * 2;
#pragma unroll
        for (int i = 0; i < 4; i++) {
            size_t ga = (size_t)rowA[i] * (Dd * 2) + kb + coff[i];
            size_t gb = (size_t)rowB[i] * (Dd * 2) + kb + coff[i];
            cp16(st + OFF_A + dsto[i], (const char*)A + ga);
            cp16(st + OFF_B + dsto[i], (const char*)B + gb);
        }
    };

    float acc[4][4][4];
#pragma unroll
    for (int mt = 0; mt < 4; mt++)
#pragma unroll
        for (int nt = 0; nt < 4; nt++)
#pragma unroll
            for (int e = 0; e < 4; e++) acc[mt][nt][e] = 0.f;

    prefetch(0); CP_COMMIT();
    prefetch(1); CP_COMMIT();

    const int a_row = wm * 64 + (lid & 15);
    const uint32_t a_cb = (uint32_t)(((lid >> 4) & 1) * 16);
    const int mg = lid >> 3;
    const int b_row0 = wn * 32 + (mg >> 1) * 8 + (lid & 7);
    const uint32_t b_cb = (uint32_t)((mg & 1) * 16);

    const int NIT = Dd / BKC;   // 16
    for (int it = 0; it < NIT; it++) {
        if (it + 1 < NIT) { CP_WAIT(1); } else { CP_WAIT(0); }
        __syncthreads();          // stage it%3 ready; reads of stage (it-1)%3 done
        if (it + 2 < NIT) { prefetch(it + 2); CP_COMMIT(); }   // targets (it-1)%3

        uint32_t st = sb + (it % 3) * STG_BYTES;
#pragma unroll
        for (int kt = 0; kt < 4; kt++) {
            uint32_t ah[4][4];
#pragma unroll
            for (int mt = 0; mt < 4; mt++) {
                uint32_t off = (uint32_t)((a_row + mt * 16) * 128) + kt * 32 + a_cb;
                off = SWZ128(off);
                ldsm_x4(ah[mt], st + OFF_A + off);
            }
            uint32_t bh[4][2];
#pragma unroll
            for (int p = 0; p < 2; p++) {
                uint32_t off = (uint32_t)((b_row0 + p * 16) * 128) + kt * 32 + b_cb;
                off = SWZ128(off);
                uint32_t r[4];
                ldsm_x4(r, st + OFF_B + off);
                bh[2 * p][0] = r[0]; bh[2 * p][1] = r[1];
                bh[2 * p + 1][0] = r[2]; bh[2 * p + 1][1] = r[3];
            }
#pragma unroll
            for (int mt = 0; mt < 4; mt++)
#pragma unroll
                for (int nt = 0; nt < 4; nt++)
                    mma_f16(acc[mt][nt], ah[mt], bh[nt]);
        }
    }

    // epilogue
#pragma unroll
    for (int nt = 0; nt < 4; nt++) {
        int c0 = n0 + wn * 32 + nt * 8 + (lid & 3) * 2;
        float b0 = bias[c0], b1 = bias[c0 + 1];
#pragma unroll
        for (int mt = 0; mt < 4; mt++) {
            int r0 = m0 + wm * 64 + mt * 16 + (lid >> 2);
            float v0 = (acc[mt][nt][0] + b0) * oscl, v1 = (acc[mt][nt][1] + b1) * oscl;
            float v2 = (acc[mt][nt][2] + b0) * oscl, v3 = (acc[mt][nt][3] + b1) * oscl;
            if (MODE == 0) {
                *(uint32_t*)&Cq[(size_t)r0 * Dd + c0] = pkh2(v0, v1);
                *(uint32_t*)&Cq[(size_t)(r0 + 8) * Dd + c0] = pkh2(v2, v3);
            } else {
                float2 w0 = {v0, v1}, w1 = {v2, v3};
                *(float2*)&C[(size_t)r0 * Dd + c0] = w0;
                *(float2*)&C[(size_t)(r0 + 8) * Dd + c0] = w1;
            }
        }
    }
}

// ================= Flash attention (all-fp16, 512 threads, 256 query rows) =====
constexpr int AT_STG = 32768;                      // K 16KB | V 16KB
constexpr int A_QZ = 3 * AT_STG;                   // Q 32K (reused for out staging)
constexpr int ATT_SMEM = A_QZ + 32768 + 1024;      // ~130KB

template<bool MASK>
__device__ __forceinline__ void attn_tile(
    uint32_t st, int kv0, int r0g, int r1g, int lid,
    int krow, uint32_t kcb, int vrow, uint32_t vcb,
    const uint32_t (&qh)[4][4],
    float (&o)[8][4], float (&lsc)[4])
{
    const uint32_t ONESB[2] = {0x3C003C00u, 0x3C003C00u};   // fp16 1.0 x4
#pragma unroll
    for (int hf = 0; hf < 4; hf++) {
        // S = Q K^T over 32 keys (already in log2 domain via pre-scaled Q)
        float s[4][4];
#pragma unroll
        for (int nt = 0; nt < 4; nt++)
#pragma unroll
            for (int e = 0; e < 4; e++) s[nt][e] = 0.f;
#pragma unroll
        for (int kd = 0; kd < 4; kd++) {
#pragma unroll
            for (int np = 0; np < 2; np++) {
                uint32_t off = SWZ128((uint32_t)((hf * 32 + np * 16 + krow) * 128) + kd * 32 + kcb);
                uint32_t kh_[4];
                ldsm_x4(kh_, st + off);            // K fp16
                mma_f16(s[2 * np],     qh[kd], kh_);
                mma_f16(s[2 * np + 1], qh[kd], kh_ + 2);
            }
        }

        // P = 2^s via half2 EX2
        uint32_t pa[2][4];
#pragma unroll
        for (int nt = 0; nt < 4; nt++) {
            float v0 = s[nt][0], v1 = s[nt][1], v2 = s[nt][2], v3 = s[nt][3];
            if (MASK) {
                int kg = kv0 + hf * 32 + nt * 8 + (lid & 3) * 2;
                v0 = (kg     <= r0g) ? v0 : -INFINITY;
                v1 = (kg + 1 <= r0g) ? v1 : -INFINITY;
                v2 = (kg     <= r1g) ? v2 : -INFINITY;
                v3 = (kg + 1 <= r1g) ? v3 : -INFINITY;
            }
            int kp = nt >> 1, e = (nt & 1) * 2;
            pa[kp][e]     = ex2_h2(pkh2(v0, v1));
            pa[kp][e + 1] = ex2_h2(pkh2(v2, v3));
        }

        // lsum += P @ ones  (exact fp32 row sums)
        mma_f16(lsc, pa[0], ONESB);
        mma_f16(lsc, pa[1], ONESB);

        // O += P V over this 32-key half
#pragma unroll
        for (int kp = 0; kp < 2; kp++) {
#pragma unroll
            for (int np = 0; np < 4; np++) {
                uint32_t off = SWZ128((uint32_t)((hf * 32 + kp * 16 + vrow) * 128) + np * 32 + vcb);
                uint32_t vh_[4];
                ldsm_x4_t(vh_, st + 16384 + off);  // V fp16
                mma_f16(o[2 * np],     pa[kp], vh_);
                mma_f16(o[2 * np + 1], pa[kp], vh_ + 2);
            }
        }
    }
}

__global__ __launch_bounds__(512, 1) void attn_mma()
{
    extern __shared__ char smc[];
    uint32_t sraw = smem_u32(smc);
    uint32_t sb = (sraw + 1023u) & ~1023u;
    char* smb = smc + (sb - sraw);

    const int tid = threadIdx.x, lid = tid & 31, wq = tid >> 5;   // 16 warps
    // global heavy-first 1-D grid: bids 0..31 are the heaviest (qi=7) CTAs
    const int qi = 7 - ((int)blockIdx.x >> 5);    // 0..7 (256 query rows each)
    const int bh = (int)blockIdx.x & 31;
    const int b = bh >> 4, h = bh & 15;
    const int q0 = qi * 256;
    const size_t base2 = ((size_t)b * Ss * Dd + (size_t)h * DH) * 2;   // bytes

    // Q load: fp16, 256 rows x 128B
#pragma unroll
    for (int i = 0; i < 4; i++) {
        int idx = tid + i * 512;
        int row = idx >> 3; uint32_t colb = (uint32_t)((idx & 7) * 16);
        const char* src = (const char*)g_q16 + base2 + (size_t)(q0 + row) * 2048 + colb;
        cp16(sb + A_QZ + SWZ128((uint32_t)(row * 128) + colb), src);
    }
    CP_COMMIT();

    const char* kvb[2] = {(const char*)g_k16, (const char*)g_v16};
    auto kvload = [&](int kt) {
        uint32_t st = sb + (kt % 3) * AT_STG;
        int kv0 = kt * 128;
#pragma unroll
        for (int i = 0; i < 4; i++) {
            int idx = tid + i * 512;
            int arr = idx >> 10, c = idx & 1023;
            int row = c >> 3; uint32_t colb = (uint32_t)((c & 7) * 16);
            cp16(st + arr * 16384 + SWZ128((uint32_t)(row * 128) + colb),
                 kvb[arr] + base2 + (size_t)(kv0 + row) * 2048 + colb);
        }
    };

    const int nkt = 2 * qi + 2;   // 128-key tiles (>= 2 always)
    kvload(0); CP_COMMIT();
    kvload(1); CP_COMMIT();
    CP_WAIT(2);          // Q done
    __syncthreads();

    // Q fragments -> registers (4 dim-chunks of 16)
    uint32_t qh[4][4];
    {
        const int a_row = wq * 16 + (lid & 15);
        const uint32_t a_cb = (uint32_t)(((lid >> 4) & 1) * 16);
#pragma unroll
        for (int kd = 0; kd < 4; kd++)
            ldsm_x4(qh[kd], sb + A_QZ + SWZ128((uint32_t)(a_row * 128) + kd * 32 + a_cb));
    }

    float o[8][4];
#pragma unroll
    for (int nt = 0; nt < 8; nt++)
#pragma unroll
        for (int e = 0; e < 4; e++) o[nt][e] = 0.f;
    float lsc[4] = {0.f, 0.f, 0.f, 0.f};

    const int r0g = q0 + wq * 16 + (lid >> 2);
    const int r1g = r0g + 8;
    const int mg = lid >> 3;
    const int krow = (mg >> 1) * 8 + (lid & 7);
    const uint32_t kcb = (uint32_t)((mg & 1) * 16);
    const int vrow = lid & 15;
    const uint32_t vcb = (uint32_t)((lid >> 4) * 16);

    const int ktfull = 2 * qi;    // tiles [0, ktfull) need no mask (last two masked)
    for (int kt = 0; kt < nkt; kt++) {
        if (kt + 1 < nkt) { CP_WAIT(1); } else { CP_WAIT(0); }
        __syncthreads();          // stage kt ready; all reads of stage (kt-1)%3 done
        if (kt + 2 < nkt) { kvload(kt + 2); CP_COMMIT(); }   // safe: targets (kt-1)%3
        uint32_t st = sb + (kt % 3) * AT_STG;
        if (kt < ktfull)
            attn_tile<false>(st, kt * 128, r0g, r1g, lid, krow, kcb, vrow, vcb,
                             qh, o, lsc);
        else
            attn_tile<true>(st, kt * 128, r0g, r1g, lid, krow, kcb, vrow, vcb,
                            qh, o, lsc);
    }

    // row sums straight from the ones-MMA accumulator
    float il0 = 1.f / lsc[0], il1 = 1.f / lsc[2];

    // epilogue: normalize, fp16, stage in smem, coalesced store
    __syncthreads();              // all tile reads done before overwriting Q region
    {
        int rs0 = wq * 16 + (lid >> 2);
#pragma unroll
        for (int nt = 0; nt < 8; nt++) {
            uint32_t colb = (uint32_t)(nt * 16 + (lid & 3) * 4);
            *(uint32_t*)(smb + A_QZ + rs0 * 128 + colb)       = pkh2(o[nt][0] * il0, o[nt][1] * il0);
            *(uint32_t*)(smb + A_QZ + (rs0 + 8) * 128 + colb) = pkh2(o[nt][2] * il1, o[nt][3] * il1);
        }
    }
    __syncthreads();
#pragma unroll
    for (int i = 0; i < 4; i++) {
        int idx = tid + i * 512;
        int row = idx >> 3; uint32_t colb = (uint32_t)((idx & 7) * 16);
        uint4 v = *(uint4*)(smb + A_QZ + row * 128 + colb);
        char* dst = (char*)g_a16 + base2 + (size_t)(q0 + row) * 2048 + colb;
        *(uint4*)dst = v;
    }
}

// ---------------- launch ----------------
extern "C" void kernel_launch(void* const* d_in, const int* in_sizes, int n_in,
                              void* d_out, int out_size)
{
    const float* x  = (const float*)d_in[0];
    const float* Wq = (const float*)d_in[1];
    const float* bq = (const float*)d_in[2];
    const float* Wk = (const float*)d_in[3];
    const float* bk = (const float*)d_in[4];
    const float* Wv = (const float*)d_in[5];
    const float* bv = (const float*)d_in[6];
    const float* Wo = (const float*)d_in[7];
    const float* bo = (const float*)d_in[8];
    float* out = (float*)d_out;

    __half *x16, *wt16;
    cudaGetSymbolAddress((void**)&x16,  g_x16);
    cudaGetSymbolAddress((void**)&wt16, g_wt16);

    cudaFuncSetAttribute(gemm_mma<0>,
                         cudaFuncAttributeMaxDynamicSharedMemorySize, GEMM_SMEM);
    cudaFuncSetAttribute(gemm_mma<1>,
                         cudaFuncAttributeMaxDynamicSharedMemorySize, GEMM_SMEM);
    cudaFuncSetAttribute(attn_mma,
                         cudaFuncAttributeMaxDynamicSharedMemorySize, ATT_SMEM);

    // fused prep: z 0..3 = transpose Wq/Wk/Wv/Wo, z 4..7 = x fp32->fp16 slices
    prep_all<<<dim3(32, 32, 8), 256>>>(x, Wq, Wk, Wv, Wo, x16, wt16);

    // Fused QKV projection: one launch, outputs routed to q16(scaled)/k16/v16
    gemm_mma<0><<<dim3(24, MM / BM), 256, GEMM_SMEM>>>(bq, bk, bv, nullptr);

    // 256 CTAs x 512 threads, 256 query rows each, global heavy-first
    attn_mma<<<256, 512, ATT_SMEM>>>();

    // Output projection
    gemm_mma<1><<<dim3(8, MM / BM), 256, GEMM_SMEM>>>(bo, nullptr, nullptr, out);
}